// round 6
// baseline (speedup 1.0000x reference)
#include <cuda_runtime.h>

#define NL   4
#define SEQ  34
#define DM   6
#define VOC  14
#define BPB  32
#define NTH  544                  /* 17 warps: warp w owns t0=w for 32 batches */
#define HROW 8                    /* 6 floats h-pairs + 2 pad: 32B row */
#define KVSTRIDE (SEQ*HROW + 4)   /* 276 floats = 69 16B-quads; 69 mod 8 = 5 -> conflict-free */
#define KVBUF (BPB*KVSTRIDE)      /* 8832 floats per buffer */

#define FMA2(d,a,b,c) asm("fma.rn.f32x2 %0, %1, %2, %3;" : "=l"(d) : "l"(a), "l"(b), "l"(c))
#define MUL2(d,a,b)   asm("mul.rn.f32x2 %0, %1, %2;"     : "=l"(d) : "l"(a), "l"(b))
#define ADD2(d,a,b)   asm("add.rn.f32x2 %0, %1, %2;"     : "=l"(d) : "l"(a), "l"(b))

__device__ __forceinline__ unsigned long long pack2(float lo, float hi) {
    unsigned long long r;
    asm("mov.b64 %0, {%1, %2};" : "=l"(r) : "f"(lo), "f"(hi));
    return r;
}
__device__ __forceinline__ void unpack2(unsigned long long v, float& lo, float& hi) {
    asm("mov.b64 {%0, %1}, %2;" : "=f"(lo), "=f"(hi) : "l"(v));
}
__device__ __forceinline__ float ex2f(float x) {
    float r; asm("ex2.approx.f32 %0, %1;" : "=f"(r) : "f"(x)); return r;
}

__global__ __launch_bounds__(NTH, 1)
void addtx_kernel(const int*   __restrict__ g_idx,
                  const float* __restrict__ g_tok,
                  const float* __restrict__ g_pos,
                  const float* __restrict__ g_lnw,
                  const float* __restrict__ g_lnb,
                  const float* __restrict__ g_q1,
                  const float* __restrict__ g_k1,
                  const float* __restrict__ g_v1,
                  const float* __restrict__ g_q2,
                  const float* __restrict__ g_k2,
                  const float* __restrict__ g_v2,
                  const float* __restrict__ g_ow,
                  const float* __restrict__ g_lnfw,
                  const float* __restrict__ g_lnfb,
                  const float* __restrict__ g_hw,
                  float* __restrict__ g_out)
{
    __shared__ float sQ1[NL*9], sK1[NL*9], sV1[NL*9];
    __shared__ float sQ2[NL*9], sK2[NL*9], sV2[NL*9];
    __shared__ float sOW[NL*36];
    __shared__ float sLNW[NL*DM], sLNB[NL*DM];
    __shared__ float sLNF[2*DM];
    __shared__ float sHW[VOC*DM];
    __shared__ float sTOK[VOC*3];
    __shared__ float sPOS[SEQ*3];
    extern __shared__ __align__(16) float sKV[];   // [2][KVBUF] double buffer

    const int tid = threadIdx.x;

    for (int i = tid; i < NL*9; i += NTH) {
        sQ1[i]=g_q1[i]; sK1[i]=g_k1[i]; sV1[i]=g_v1[i];
        sQ2[i]=g_q2[i]; sK2[i]=g_k2[i]; sV2[i]=g_v2[i];
    }
    for (int i = tid; i < NL*36; i += NTH) sOW[i]=g_ow[i];
    for (int i = tid; i < NL*DM; i += NTH) { sLNW[i]=g_lnw[i]; sLNB[i]=g_lnb[i]; }
    if (tid < DM) { sLNF[tid]=g_lnfw[tid]; sLNF[DM+tid]=g_lnfb[tid]; }
    for (int i = tid; i < VOC*DM; i += NTH) sHW[i]=g_hw[i];
    for (int i = tid; i < VOC*3; i += NTH) sTOK[i]=g_tok[i];
    for (int i = tid; i < SEQ*3; i += NTH) sPOS[i]=g_pos[i];

    const int t0 = tid >> 5;            // warp id = first query position (0..16)
    const int bl = tid & 31;            // lane = batch within block
    const int b  = blockIdx.x * BPB + bl;
    const int tA = t0, tB = t0 + 17;

    __syncthreads();

    const int tokA = g_idx[b*SEQ + tA];
    const int tokB = g_idx[b*SEQ + tB];
    float xA[DM], xB[DM];
    #pragma unroll
    for (int d = 0; d < 3; d++) {
        xA[d] = sTOK[tokA*3+d]; xA[3+d] = sPOS[tA*3+d];
        xB[d] = sTOK[tokB*3+d]; xB[3+d] = sPOS[tB*3+d];
    }

    const int kvoff = bl*KVSTRIDE;
    const float QS = 0.5773502691896258f * 1.4426950408889634f;  // 1/sqrt(3)*log2(e)

    #pragma unroll 1
    for (int l = 0; l < NL; l++) {
        float* kvb = sKV + (l & 1)*KVBUF + kvoff;
        const float* lw = &sLNW[l*DM];
        const float* lb = &sLNB[l*DM];

        // ---- layernorm both queries ----
        float hA[DM], hB[DM];
        {
            float m = (xA[0]+xA[1]+xA[2]+xA[3]+xA[4]+xA[5]) * (1.0f/6.0f);
            float v = 0.f;
            #pragma unroll
            for (int d=0; d<DM; d++) { float dd = xA[d]-m; v += dd*dd; hA[d]=dd; }
            float r = rsqrtf(v*(1.0f/6.0f) + 1e-5f);
            #pragma unroll
            for (int d=0; d<DM; d++) hA[d] = hA[d]*r*lw[d] + lb[d];
        }
        {
            float m = (xB[0]+xB[1]+xB[2]+xB[3]+xB[4]+xB[5]) * (1.0f/6.0f);
            float v = 0.f;
            #pragma unroll
            for (int d=0; d<DM; d++) { float dd = xB[d]-m; v += dd*dd; hB[d]=dd; }
            float r = rsqrtf(v*(1.0f/6.0f) + 1e-5f);
            #pragma unroll
            for (int d=0; d<DM; d++) hB[d] = hB[d]*r*lw[d] + lb[d];
        }

        // ---- stage both h rows (head-pair interleaved) ----
        {
            float4* dA = reinterpret_cast<float4*>(kvb + tA*HROW);
            dA[0] = make_float4(hA[0],hA[3],hA[1],hA[4]);
            *reinterpret_cast<float2*>(kvb + tA*HROW + 4) = make_float2(hA[2],hA[5]);
            float4* dB = reinterpret_cast<float4*>(kvb + tB*HROW);
            dB[0] = make_float4(hB[0],hB[3],hB[1],hB[4]);
            *reinterpret_cast<float2*>(kvb + tB*HROW + 4) = make_float2(hB[2],hB[5]);
        }

        // ---- u = W_k^T (W_q h) per head per query (log2-domain scale folded) ----
        unsigned long long uA0,uA1,uA2, uB0,uB1,uB2;
        {
            float q1[3], q2[3];
            #pragma unroll
            for (int d=0; d<3; d++) {
                const float* ww;
                ww = &sQ1[l*9+d*3]; q1[d] = (ww[0]*hA[0]+ww[1]*hA[1]+ww[2]*hA[2]) * QS;
                ww = &sQ2[l*9+d*3]; q2[d] = (ww[0]*hA[3]+ww[1]*hA[4]+ww[2]*hA[5]) * QS;
            }
            uA0 = pack2(sK1[l*9+0]*q1[0]+sK1[l*9+3]*q1[1]+sK1[l*9+6]*q1[2],
                        sK2[l*9+0]*q2[0]+sK2[l*9+3]*q2[1]+sK2[l*9+6]*q2[2]);
            uA1 = pack2(sK1[l*9+1]*q1[0]+sK1[l*9+4]*q1[1]+sK1[l*9+7]*q1[2],
                        sK2[l*9+1]*q2[0]+sK2[l*9+4]*q2[1]+sK2[l*9+7]*q2[2]);
            uA2 = pack2(sK1[l*9+2]*q1[0]+sK1[l*9+5]*q1[1]+sK1[l*9+8]*q1[2],
                        sK2[l*9+2]*q2[0]+sK2[l*9+5]*q2[1]+sK2[l*9+8]*q2[2]);
            #pragma unroll
            for (int d=0; d<3; d++) {
                const float* ww;
                ww = &sQ1[l*9+d*3]; q1[d] = (ww[0]*hB[0]+ww[1]*hB[1]+ww[2]*hB[2]) * QS;
                ww = &sQ2[l*9+d*3]; q2[d] = (ww[0]*hB[3]+ww[1]*hB[4]+ww[2]*hB[5]) * QS;
            }
            uB0 = pack2(sK1[l*9+0]*q1[0]+sK1[l*9+3]*q1[1]+sK1[l*9+6]*q1[2],
                        sK2[l*9+0]*q2[0]+sK2[l*9+3]*q2[1]+sK2[l*9+6]*q2[2]);
            uB1 = pack2(sK1[l*9+1]*q1[0]+sK1[l*9+4]*q1[1]+sK1[l*9+7]*q1[2],
                        sK2[l*9+1]*q2[0]+sK2[l*9+4]*q2[1]+sK2[l*9+7]*q2[2]);
            uB2 = pack2(sK1[l*9+2]*q1[0]+sK1[l*9+5]*q1[1]+sK1[l*9+8]*q1[2],
                        sK2[l*9+2]*q2[0]+sK2[l*9+5]*q2[1]+sK2[l*9+8]*q2[2]);
        }
        __syncthreads();   // the ONLY barrier this layer

        // ---- phase 1: j = 0..t0, BOTH queries (warp-uniform, no masks) ----
        unsigned long long denA=0, aA0=0, aA1=0, aA2=0;
        unsigned long long denB=0, aB0=0, aB1=0, aB2=0;
        const float* rowp = kvb;
        #pragma unroll 2
        for (int j = 0; j <= t0; j++) {
            ulonglong2 r01 = *reinterpret_cast<const ulonglong2*>(rowp);
            unsigned long long hp2 = *reinterpret_cast<const unsigned long long*>(rowp + 4);
            unsigned long long sA, sB;
            MUL2(sA, uA0, r01.x); FMA2(sA, uA1, r01.y, sA); FMA2(sA, uA2, hp2, sA);
            MUL2(sB, uB0, r01.x); FMA2(sB, uB1, r01.y, sB); FMA2(sB, uB2, hp2, sB);
            float a1,a2,b1,b2; unpack2(sA,a1,a2); unpack2(sB,b1,b2);
            unsigned long long eA = pack2(ex2f(a1), ex2f(a2));
            unsigned long long eB = pack2(ex2f(b1), ex2f(b2));
            ADD2(denA, denA, eA);
            FMA2(aA0, eA, r01.x, aA0); FMA2(aA1, eA, r01.y, aA1); FMA2(aA2, eA, hp2, aA2);
            ADD2(denB, denB, eB);
            FMA2(aB0, eB, r01.x, aB0); FMA2(aB1, eB, r01.y, aB1); FMA2(aB2, eB, hp2, aB2);
            rowp += HROW;
        }

        // ---- query A epilogue ----
        {
            float d1, d2; unpack2(denA, d1, d2);
            float i1 = 1.0f/d1, i2 = 1.0f/d2;
            float h1[3], h2[3];
            unpack2(aA0, h1[0], h2[0]); unpack2(aA1, h1[1], h2[1]); unpack2(aA2, h1[2], h2[2]);
            float o[6];
            #pragma unroll
            for (int d=0; d<3; d++) {
                const float* w1 = &sV1[l*9+d*3];
                const float* w2 = &sV2[l*9+d*3];
                o[d]   = (w1[0]*h1[0]+w1[1]*h1[1]+w1[2]*h1[2]) * i1;
                o[3+d] = (w2[0]*h2[0]+w2[1]*h2[1]+w2[2]*h2[2]) * i2;
            }
            #pragma unroll
            for (int d=0; d<DM; d++) {
                float acc = xA[d];
                const float* ww = &sOW[l*36 + d*DM];
                #pragma unroll
                for (int e=0; e<DM; e++) acc += ww[e]*o[e];
                xA[d] = acc;
            }
        }

        // ---- phase 2: 17 uniform steps, query B only ----
        #pragma unroll 4
        for (int j = 0; j < 17; j++) {
            ulonglong2 r01 = *reinterpret_cast<const ulonglong2*>(rowp);
            unsigned long long hp2 = *reinterpret_cast<const unsigned long long*>(rowp + 4);
            unsigned long long sB;
            MUL2(sB, uB0, r01.x); FMA2(sB, uB1, r01.y, sB); FMA2(sB, uB2, hp2, sB);
            float b1,b2; unpack2(sB,b1,b2);
            unsigned long long eB = pack2(ex2f(b1), ex2f(b2));
            ADD2(denB, denB, eB);
            FMA2(aB0, eB, r01.x, aB0); FMA2(aB1, eB, r01.y, aB1); FMA2(aB2, eB, hp2, aB2);
            rowp += HROW;
        }

        // ---- query B epilogue ----
        {
            float d1, d2; unpack2(denB, d1, d2);
            float i1 = 1.0f/d1, i2 = 1.0f/d2;
            float h1[3], h2[3];
            unpack2(aB0, h1[0], h2[0]); unpack2(aB1, h1[1], h2[1]); unpack2(aB2, h1[2], h2[2]);
            float o[6];
            #pragma unroll
            for (int d=0; d<3; d++) {
                const float* w1 = &sV1[l*9+d*3];
                const float* w2 = &sV2[l*9+d*3];
                o[d]   = (w1[0]*h1[0]+w1[1]*h1[1]+w1[2]*h1[2]) * i1;
                o[3+d] = (w2[0]*h2[0]+w2[1]*h2[1]+w2[2]*h2[2]) * i2;
            }
            #pragma unroll
            for (int d=0; d<DM; d++) {
                float acc = xB[d];
                const float* ww = &sOW[l*36 + d*DM];
                #pragma unroll
                for (int e=0; e<DM; e++) acc += ww[e]*o[e];
                xB[d] = acc;
            }
        }
        // no trailing barrier: next layer writes the other buffer
    }

    // ---- final layernorm + vocab head, both queries ----
    #pragma unroll
    for (int qq = 0; qq < 2; qq++) {
        float* x = qq ? xB : xA;
        int    t = qq ? tB : tA;
        float mean = (x[0]+x[1]+x[2]+x[3]+x[4]+x[5]) * (1.0f/6.0f);
        float var = 0.f; float h[DM];
        #pragma unroll
        for (int d=0; d<DM; d++) { float dd=x[d]-mean; var+=dd*dd; h[d]=dd; }
        float r = rsqrtf(var*(1.0f/6.0f)+1e-5f);
        #pragma unroll
        for (int d=0; d<DM; d++) h[d] = h[d]*r*sLNF[d] + sLNF[DM+d];

        float* op = g_out + (size_t)(b*SEQ + t)*VOC;
        #pragma unroll
        for (int c = 0; c < VOC; c += 2) {
            float l0=0.f, l1=0.f;
            #pragma unroll
            for (int d=0; d<DM; d++) {
                l0 += sHW[c*DM+d]*h[d];
                l1 += sHW[(c+1)*DM+d]*h[d];
            }
            *reinterpret_cast<float2*>(op + c) = make_float2(l0,l1);
        }
    }
}

extern "C" void kernel_launch(void* const* d_in, const int* in_sizes, int n_in,
                              void* d_out, int out_size) {
    const int* idx = (const int*)d_in[0];
    int nb   = in_sizes[0] / SEQ;          // 16384
    int grid = nb / BPB;                   // 512 blocks of 544 threads
    int dyn  = 2*KVBUF*(int)sizeof(float); // 70656 B double-buffered KV
    cudaFuncSetAttribute(addtx_kernel, cudaFuncAttributeMaxDynamicSharedMemorySize, dyn);
    addtx_kernel<<<grid, NTH, dyn>>>(idx,
        (const float*)d_in[1],  (const float*)d_in[2],  (const float*)d_in[3],
        (const float*)d_in[4],  (const float*)d_in[5],  (const float*)d_in[6],
        (const float*)d_in[7],  (const float*)d_in[8],  (const float*)d_in[9],
        (const float*)d_in[10], (const float*)d_in[11], (const float*)d_in[12],
        (const float*)d_in[13], (const float*)d_in[14], (float*)d_out);
}